// round 1
// baseline (speedup 1.0000x reference)
#include <cuda_runtime.h>

#define K_CODES 16384
#define NSAMP   4096
#define DIM     14
#define HW      1024
#define Q_ELEMS (4 * DIM * HW)   // 57344

__device__ float g_avg[K_CODES];   // sum of probs per code (over all samples)
__device__ float g_ent[NSAMP];     // per-sample entropy

__global__ void zero_kernel() {
    int i = blockIdx.x * blockDim.x + threadIdx.x;
    if (i < K_CODES) g_avg[i] = 0.0f;
}

// q = sign(x): coalesced elementwise
__global__ void sign_kernel(const float* __restrict__ x, float* __restrict__ out, int n) {
    int i = blockIdx.x * blockDim.x + threadIdx.x;
    if (i < n) out[i] = (x[i] > 0.0f) ? 1.0f : -1.0f;
}

// One block per sample: index, entropy, avg_probs accumulation.
__global__ __launch_bounds__(256) void sample_kernel(const float* __restrict__ x,
                                                     float* __restrict__ out,
                                                     int out_size) {
    __shared__ float sxn[DIM];
    __shared__ float sL[128];
    __shared__ float sH[128];
    __shared__ float red[256];

    const int s   = blockIdx.x;        // sample id 0..4095
    const int b   = s >> 10;
    const int n   = s & (HW - 1);
    const int tid = threadIdx.x;

    // ---- load 14 channel values, normalize, emit index (thread 0) ----
    if (tid == 0) {
        float v[DIM];
        float ss = 0.0f;
        int idx = 0;
#pragma unroll
        for (int j = 0; j < DIM; j++) {
            v[j] = x[(b * DIM + j) * HW + n];
            ss += v[j] * v[j];
            if (v[j] > 0.0f) idx |= (1 << (13 - j));   // big-endian bit order
        }
        float inv = rsqrtf(ss);
#pragma unroll
        for (int j = 0; j < DIM; j++) sxn[j] = v[j] * inv;
        if (out_size >= Q_ELEMS + 1 + NSAMP)
            out[Q_ELEMS + 1 + s] = (float)idx;
    }
    __syncthreads();

    // ---- Walsh half tables: L over bits 0..6, H over bits 7..13 ----
    if (tid < 128) {
        int m = tid;
        float a = 0.0f;
#pragma unroll
        for (int j = 0; j < 7; j++) a += ((m >> j) & 1) ? sxn[j] : -sxn[j];
        sL[m] = a;
    } else {
        int m = tid - 128;
        float a = 0.0f;
#pragma unroll
        for (int j = 0; j < 7; j++) a += ((m >> j) & 1) ? sxn[7 + j] : -sxn[7 + j];
        sH[m] = a;
    }
    __syncthreads();

    // Per-thread code set: k = i*256 + tid, i = 0..63.
    // k & 127 == tid & 127 (constant per thread); k >> 7 == 2*i + (tid >> 7).
    const float Lc  = sL[tid & 127];
    const int   hi0 = tid >> 7;

    // ---- pass 1: max of unscaled dot ----
    float M = -1e30f;
#pragma unroll 8
    for (int i = 0; i < 64; i++)
        M = fmaxf(M, Lc + sH[2 * i + hi0]);

    red[tid] = M;
    __syncthreads();
    for (int off = 128; off > 0; off >>= 1) {
        if (tid < off) red[tid] = fmaxf(red[tid], red[tid + off]);
        __syncthreads();
    }
    const float Mu = red[0];
    __syncthreads();

    // ---- pass 2: S = sum exp(dz), T = sum dz*exp(dz), dz = 200*(dot - max) <= 0 ----
    // Threshold dz > -30: skipped terms have exp < 1e-13, below the reference's
    // own fp32 accumulation granularity (S >= 1).
    float Sp = 0.0f, Tp = 0.0f;
#pragma unroll 8
    for (int i = 0; i < 64; i++) {
        float dz = 200.0f * (Lc + sH[2 * i + hi0] - Mu);
        if (dz > -30.0f) {
            float e = __expf(dz);
            Sp += e;
            Tp += dz * e;
        }
    }
    red[tid] = Sp;
    __syncthreads();
    for (int off = 128; off > 0; off >>= 1) {
        if (tid < off) red[tid] += red[tid + off];
        __syncthreads();
    }
    const float S = red[0];
    __syncthreads();
    red[tid] = Tp;
    __syncthreads();
    for (int off = 128; off > 0; off >>= 1) {
        if (tid < off) red[tid] += red[tid + off];
        __syncthreads();
    }
    const float T = red[0];
    __syncthreads();

    if (tid == 0) {
        // entropy = lse - E[z] = (M + logS) - (M + T/S) = logS - T/S
        g_ent[s] = logf(S) - T / S;
    }

    // ---- pass 3: accumulate probs into g_avg (sparse thanks to peaked softmax) ----
    const float invS = 1.0f / S;
#pragma unroll 8
    for (int i = 0; i < 64; i++) {
        float dz = 200.0f * (Lc + sH[2 * i + hi0] - Mu);
        if (dz > -30.0f) {
            int k = i * 256 + tid;
            atomicAdd(&g_avg[k], __expf(dz) * invS);
        }
    }
}

// Single block: reduce entropy mean + codebook-usage entropy -> el scalar
__global__ __launch_bounds__(256) void finalize_kernel(float* __restrict__ out, int out_size) {
    __shared__ float red[256];
    const int tid = threadIdx.x;

    // sum of per-sample entropies
    float es = 0.0f;
#pragma unroll
    for (int i = 0; i < NSAMP / 256; i++) es += g_ent[i * 256 + tid];

    // sum_k avg*log(avg+eps)  (negative number; mean_entro = -this)
    float ms = 0.0f;
    const float scale = 1.0f / (float)NSAMP;
#pragma unroll
    for (int i = 0; i < K_CODES / 256; i++) {
        float a = g_avg[i * 256 + tid] * scale;
        ms += a * logf(a + 1e-9f);
    }

    red[tid] = es;
    __syncthreads();
    for (int off = 128; off > 0; off >>= 1) {
        if (tid < off) red[tid] += red[tid + off];
        __syncthreads();
    }
    const float ent_sum = red[0];
    __syncthreads();
    red[tid] = ms;
    __syncthreads();
    for (int off = 128; off > 0; off >>= 1) {
        if (tid < off) red[tid] += red[tid + off];
        __syncthreads();
    }
    if (tid == 0 && out_size >= Q_ELEMS + 1) {
        // el = entro_mean - mean_entro = ent_sum/NSAMP + sum a*log(a+eps)
        out[Q_ELEMS] = ent_sum * (1.0f / (float)NSAMP) + red[0];
    }
}

extern "C" void kernel_launch(void* const* d_in, const int* in_sizes, int n_in,
                              void* d_out, int out_size) {
    const float* x = (const float*)d_in[0];
    float* out = (float*)d_out;

    zero_kernel<<<(K_CODES + 255) / 256, 256>>>();
    int qn = Q_ELEMS;
    if (qn > out_size) qn = out_size;
    sign_kernel<<<(qn + 255) / 256, 256>>>(x, out, qn);
    sample_kernel<<<NSAMP, 256>>>(x, out, out_size);
    finalize_kernel<<<1, 256>>>(out, out_size);
}